// round 15
// baseline (speedup 1.0000x reference)
#include <cuda_runtime.h>
#include <math.h>
#include <stdint.h>

#define BB 8
#define HH 8
#define PP 4
#define FEAT 64
#define EMB 32
#define HIN 96
#define GH 32
#define TT 101770

#define TPB 256
#define NT 128
#define STR 36                       // chunk/genW2/hmid row stride (words): 36 mod 32 = 4
#define HSTR 100                     // hin row stride: 100 mod 32 = 4
#define CHBUF (NT * STR)             // 4608 floats per chunk buffer

// smem offsets (floats)
#define SM_HIN   (2 * CHBUF)         // 32*100 = 3200
#define SM_HMID  (SM_HIN + 32 * HSTR)        // 32*36 = 1152
#define SM_ATTB  (SM_HMID + 32 * STR)        // 2*128
#define SM_B2    (SM_ATTB + 256)             // 2*128
#define SM_GATE  (SM_B2 + 256)               // 64
#define SM_TOT_F (SM_GATE + 64)

// ---------- persistent scratch ----------
__device__ float g_h1[BB * 128];
__device__ __align__(16) float g_feats[BB * FEAT];       // [b][k]
__device__ __align__(16) float g_hmidPB[HH * 32 * GH];   // [h][pb][j]
__device__ float g_gate[HH * BB];                        // [h][b]

// ---------- helpers ----------
__device__ __forceinline__ void cp16(uint32_t dst, const void* src) {
    asm volatile("cp.async.cg.shared.global [%0], [%1], 16;" :: "r"(dst), "l"(src));
}
__device__ __forceinline__ void cp4(uint32_t dst, const void* src) {
    asm volatile("cp.async.ca.shared.global [%0], [%1], 4;" :: "r"(dst), "l"(src));
}
__device__ __forceinline__ void cp_commit() { asm volatile("cp.async.commit_group;"); }
template<int N>
__device__ __forceinline__ void cp_wait() {
    asm volatile("cp.async.wait_group %0;" :: "n"(N));
}
__device__ __forceinline__ uint32_t f2tf(float f) {
    uint32_t r;
    asm("cvt.rna.tf32.f32 %0, %1;" : "=r"(r) : "f"(f));
    return r;
}
__device__ __forceinline__ void mma8(float* d, uint32_t a0, uint32_t a1,
                                     uint32_t a2, uint32_t a3,
                                     uint32_t b0, uint32_t b1) {
    asm volatile(
        "mma.sync.aligned.m16n8k8.row.col.f32.tf32.tf32.f32 "
        "{%0,%1,%2,%3}, {%4,%5,%6,%7}, {%8,%9}, {%0,%1,%2,%3};"
        : "+f"(d[0]), "+f"(d[1]), "+f"(d[2]), "+f"(d[3])
        : "r"(a0), "r"(a1), "r"(a2), "r"(a3), "r"(b0), "r"(b1));
}

// ---------- prep 1a: layer 1 ----------
__global__ void __launch_bounds__(256, 1)
prep1a_kernel(const float* __restrict__ x,
              const float* __restrict__ feW1, const float* __restrict__ feb1)
{
    int g = blockIdx.x * 8 + (threadIdx.x >> 5);
    int lane = threadIdx.x & 31;
    int b = g >> 7, j = g & 127;
    const float* xr = x + b * 784;
    const float* wr = feW1 + j * 784;
    float s = 0.f;
    #pragma unroll 4
    for (int i = lane; i < 784; i += 32) s = fmaf(xr[i], wr[i], s);
    #pragma unroll
    for (int o = 16; o; o >>= 1) s += __shfl_down_sync(0xFFFFFFFFu, s, o);
    if (lane == 0) g_h1[b * 128 + j] = fmaxf(s + feb1[j], 0.f);
}

// ---------- prep fuse: layer2 + gate + hmid(pb-major) ----------
__global__ void __launch_bounds__(256, 1)
prep_fuse_kernel(const float* __restrict__ feW2, const float* __restrict__ feb2,
                 const float* __restrict__ gateW, const float* __restrict__ gateb,
                 const float* __restrict__ embeds,
                 const float* __restrict__ genW1, const float* __restrict__ genb1)
{
    int h = blockIdx.x;
    int tid = threadIdx.x;
    __shared__ float s_h1[BB * 128];
    __shared__ float s_w2[FEAT * 128];
    __shared__ float s_feats[BB * FEAT];
    __shared__ float s_emb[PP * EMB];

    for (int i = tid; i < BB * 128; i += 256) s_h1[i] = g_h1[i];
    for (int i = tid; i < FEAT * 128; i += 256) s_w2[i] = feW2[i];
    for (int i = tid; i < PP * EMB; i += 256) s_emb[i] = embeds[i];
    __syncthreads();

    for (int o = tid; o < BB * FEAT; o += 256) {
        int b = o & 7, f = o >> 3;
        float s = feb2[f];
        const float* hr = s_h1 + b * 128;
        const float* wr = s_w2 + f * 128;
        #pragma unroll 8
        for (int j = 0; j < 128; j++) s = fmaf(hr[j], wr[j], s);
        s_feats[b * FEAT + f] = s;
        if (h == 0) g_feats[b * FEAT + f] = s;
    }
    __syncthreads();

    if (h == 0 && tid < 8) {
        int r = tid;
        float lg[8];
        float mx = -1e30f;
        #pragma unroll
        for (int c = 0; c < 8; c++) {
            float s = gateb[c];
            const float* fr = s_feats + r * FEAT;
            const float* wr = gateW + c * FEAT;
            #pragma unroll 8
            for (int k = 0; k < FEAT; k++) s = fmaf(fr[k], wr[k], s);
            lg[c] = s;
            mx = fmaxf(mx, s);
        }
        float den = 0.f;
        #pragma unroll
        for (int c = 0; c < 8; c++) { lg[c] = __expf(lg[c] - mx); den += lg[c]; }
        float inv = 1.f / den;
        #pragma unroll
        for (int c = 0; c < 8; c++) g_gate[r * 8 + c] = lg[c] * inv;
    }

    // hmid for head h, pb-major: g_hmidPB[h][pb][j]
    for (int idx = tid; idx < 32 * GH; idx += 256) {
        int pb = idx >> 5;
        int j = idx & 31;
        int p = pb >> 3, b = pb & 7;
        const float* w = genW1 + (size_t)(h * GH + j) * HIN;
        float s = genb1[h * GH + j];
        const float* fr = s_feats + b * FEAT;
        #pragma unroll 8
        for (int i = 0; i < FEAT; i++) s = fmaf(fr[i], w[i], s);
        const float* er = s_emb + p * EMB;
        #pragma unroll 8
        for (int i = 0; i < EMB; i++) s = fmaf(er[i], w[FEAT + i], s);
        g_hmidPB[h * 1024 + pb * 32 + j] = fmaxf(s, 0.f);
    }
}

// ---------- main kernel: tf32 mma.sync, 8 warps, 1 barrier/phase ----------
__global__ void __launch_bounds__(TPB, 3)
main_kernel(const float* __restrict__ genW2, const float* __restrict__ genb2,
            const float* __restrict__ attW,  const float* __restrict__ attb,
            const float* __restrict__ embeds,
            float* __restrict__ out)
{
    extern __shared__ float sm[];
    float* sm_hin  = sm + SM_HIN;
    float* sm_hmid = sm + SM_HMID;
    float* sm_attb = sm + SM_ATTB;
    float* sm_b2   = sm + SM_B2;
    float* sm_gate = sm + SM_GATE;

    int tid = threadIdx.x;
    int w   = tid >> 5;       // warp 0..7 -> m16 tile w (rows w*16..w*16+15)
    int lane = tid & 31;
    int g   = lane >> 2;      // groupID 0..7
    int tig = lane & 3;       // thread-in-group 0..3
    int t_base = blockIdx.x * NT;

    uint32_t smem_u32 = (uint32_t)__cvta_generic_to_shared(sm);

    // stage phase ph = h*4+c into buffer ph&1
    auto issue_phase = [&](int ph) {
        int h = ph >> 2, c = ph & 3;
        uint32_t chb = smem_u32 + (uint32_t)((ph & 1) * CHBUF) * 4;
        if (c < 3) {
            const float* src = attW + (size_t)h * TT * HIN + c * 32;
            #pragma unroll
            for (int i = 0; i < 4; i++) {
                int v = tid + i * TPB;          // [0, 1024)
                int row = v >> 3, cc = v & 7;
                int tr = t_base + row; if (tr >= TT) tr = TT - 1;
                cp16(chb + (uint32_t)(row * STR + cc * 4) * 4,
                     src + (size_t)tr * HIN + cc * 4);
            }
            if (c == 0 && tid < 128) {
                int tr = t_base + tid; if (tr >= TT) tr = TT - 1;
                uint32_t slot = (uint32_t)((h & 1) * 128 + tid) * 4;
                cp4(smem_u32 + (uint32_t)SM_ATTB * 4 + slot, attb  + (size_t)h * TT + tr);
                cp4(smem_u32 + (uint32_t)SM_B2   * 4 + slot, genb2 + (size_t)h * TT + tr);
            }
        } else {
            const float* src = genW2 + (size_t)h * TT * GH;
            #pragma unroll
            for (int i = 0; i < 4; i++) {
                int v = tid + i * TPB;
                int row = v >> 3, cc = v & 7;
                int tr = t_base + row; if (tr >= TT) tr = TT - 1;
                cp16(chb + (uint32_t)(row * STR + cc * 4) * 4,
                     src + (size_t)tr * GH + cc * 4);
            }
            const float* hs = g_hmidPB + (size_t)h * 1024;
            if (tid < 256) {
                int pb = tid >> 3, cc = tid & 7;
                cp16(smem_u32 + (uint32_t)(SM_HMID + pb * STR + cc * 4) * 4,
                     hs + pb * 32 + cc * 4);
            }
        }
    };

    issue_phase(0);
    cp_commit();

    // stage hin [pb][k] (stride 100) + gate
    for (int v = tid; v < 32 * 24; v += TPB) {
        int pb = v / 24, c4 = v % 24;
        int p = pb >> 3, b = pb & 7;
        float4 val = (c4 < 16)
            ? *reinterpret_cast<const float4*>(g_feats + b * FEAT + c4 * 4)
            : *reinterpret_cast<const float4*>(embeds + p * EMB + (c4 - 16) * 4);
        *reinterpret_cast<float4*>(sm_hin + pb * HSTR + c4 * 4) = val;
    }
    if (tid < HH * BB) sm_gate[tid] = g_gate[tid];

    float zacc[16], wacc[16], acc[16];
    #pragma unroll
    for (int i = 0; i < 16; i++) acc[i] = 0.f;

    for (int ph = 0; ph < 32; ph++) {
        cp_wait<0>();          // this thread's copies for group ph complete
        __syncthreads();       // all threads' copies visible; prev compute done
        if (ph < 31) { issue_phase(ph + 1); cp_commit(); }

        int h = ph >> 2, c = ph & 3;
        const float* chb = sm + (ph & 1) * CHBUF;

        if (c < 3) {
            if (c == 0) {
                #pragma unroll
                for (int i = 0; i < 16; i++) zacc[i] = 0.f;
            }
            #pragma unroll
            for (int ks = 0; ks < 4; ks++) {
                int col = ks * 8 + tig;
                uint32_t B0[4], B1[4];
                #pragma unroll
                for (int nt = 0; nt < 4; nt++) {
                    const float* hp = sm_hin + (nt * 8 + g) * HSTR + c * 32 + col;
                    B0[nt] = f2tf(hp[0]);
                    B1[nt] = f2tf(hp[4]);
                }
                uint32_t A[4];
                {
                    const float* ap  = chb + (w * 16 + g) * STR + col;
                    const float* ap8 = ap + 8 * STR;
                    A[0] = f2tf(ap[0]);
                    A[1] = f2tf(ap8[0]);
                    A[2] = f2tf(ap[4]);
                    A[3] = f2tf(ap8[4]);
                }
                #pragma unroll
                for (int nt = 0; nt < 4; nt++)
                    mma8(&zacc[nt * 4], A[0], A[1], A[2], A[3], B0[nt], B1[nt]);
            }
        } else {
            #pragma unroll
            for (int i = 0; i < 16; i++) wacc[i] = 0.f;
            #pragma unroll
            for (int ks = 0; ks < 4; ks++) {
                int col = ks * 8 + tig;
                uint32_t B0[4], B1[4];
                #pragma unroll
                for (int nt = 0; nt < 4; nt++) {
                    const float* hp = sm_hmid + (nt * 8 + g) * STR + col;
                    B0[nt] = f2tf(hp[0]);
                    B1[nt] = f2tf(hp[4]);
                }
                uint32_t A[4];
                {
                    const float* ap  = chb + (w * 16 + g) * STR + col;
                    const float* ap8 = ap + 8 * STR;
                    A[0] = f2tf(ap[0]);
                    A[1] = f2tf(ap8[0]);
                    A[2] = f2tf(ap[4]);
                    A[3] = f2tf(ap8[4]);
                }
                #pragma unroll
                for (int nt = 0; nt < 4; nt++)
                    mma8(&wacc[nt * 4], A[0], A[1], A[2], A[3], B0[nt], B1[nt]);
            }

            // ---- epilogue for head h ----
            int par = h & 1;
            float ab[2], bb[2];
            #pragma unroll
            for (int rr = 0; rr < 2; rr++) {
                int tl = w * 16 + rr * 8 + g;
                ab[rr] = sm_attb[par * 128 + tl];
                bb[rr] = sm_b2[par * 128 + tl];
            }
            float gr0 = sm_gate[h * BB + 2 * tig];
            float gr1 = sm_gate[h * BB + 2 * tig + 1];
            #pragma unroll
            for (int nt = 0; nt < 4; nt++)
                #pragma unroll
                for (int r = 0; r < 4; r++) {
                    int idx = nt * 4 + r;
                    int rr = r >> 1;
                    float z = zacc[idx] + ab[rr];
                    float wv = wacc[idx] + bb[rr];
                    float imp = __fdividef(1.f, 1.f + __expf(-z));
                    float gv = (r & 1) ? gr1 : gr0;
                    acc[idx] = fmaf(wv * imp, gv, acc[idx]);
                }
        }
    }

    // ---- store: acc fragment layout -> out[b][p][t] ----
    #pragma unroll
    for (int r = 0; r < 4; r++) {
        int tl = w * 16 + (r >> 1) * 8 + g;
        int t = t_base + tl;
        if (t < TT) {
            int bo = 2 * tig + (r & 1);
            #pragma unroll
            for (int nt = 0; nt < 4; nt++)
                out[(size_t)bo * (PP * TT) + (size_t)nt * TT + t] = acc[nt * 4 + r];
        }
    }
}

extern "C" void kernel_launch(void* const* d_in, const int* in_sizes, int n_in,
                              void* d_out, int out_size)
{
    const float* x     = (const float*)d_in[0];
    const float* feW1  = (const float*)d_in[1];
    const float* feb1  = (const float*)d_in[2];
    const float* feW2  = (const float*)d_in[3];
    const float* feb2  = (const float*)d_in[4];
    const float* emb   = (const float*)d_in[5];
    const float* genW1 = (const float*)d_in[6];
    const float* genb1 = (const float*)d_in[7];
    const float* genW2 = (const float*)d_in[8];
    const float* genb2 = (const float*)d_in[9];
    const float* attW  = (const float*)d_in[10];
    const float* attb  = (const float*)d_in[11];
    const float* gateW = (const float*)d_in[12];
    const float* gateb = (const float*)d_in[13];
    float* out = (float*)d_out;

    prep1a_kernel<<<128, 256>>>(x, feW1, feb1);
    prep_fuse_kernel<<<8, 256>>>(feW2, feb2, gateW, gateb, emb, genW1, genb1);

    const int SMEM = SM_TOT_F * 4;
    cudaFuncSetAttribute(main_kernel, cudaFuncAttributeMaxDynamicSharedMemorySize, SMEM);
    int grid = (TT + NT - 1) / NT;
    main_kernel<<<grid, TPB, SMEM>>>(genW2, genb2, attW, attb, emb, out);
}

// round 16
// speedup vs baseline: 1.0587x; 1.0587x over previous
#include <cuda_runtime.h>
#include <math.h>
#include <stdint.h>

#define BB 8
#define HH 8
#define PP 4
#define FEAT 64
#define EMB 32
#define HIN 96
#define GH 32
#define TT 101770

#define TPB 128
#define NT 128
#define STR 36                       // chunk/genW2/hmid row stride (words): 36 mod 32 = 4
#define HSTR 100                     // hin row stride: 100 mod 32 = 4
#define CHBUF (NT * STR)             // 4608 floats per chunk buffer

// smem offsets (floats)
#define SM_HIN   (2 * CHBUF)         // 32*100 = 3200
#define SM_HMID  (SM_HIN + 32 * HSTR)        // 32*36 = 1152
#define SM_ATTB  (SM_HMID + 32 * STR)        // 2*128
#define SM_B2    (SM_ATTB + 256)             // 2*128
#define SM_GATE  (SM_B2 + 256)               // 64
#define SM_TOT_F (SM_GATE + 64)

// ---------- persistent scratch ----------
__device__ float g_h1[BB * 128];
__device__ __align__(16) float g_feats[BB * FEAT];          // [b][k]
__device__ __align__(16) uint32_t g_hmidPB[HH * 32 * GH];   // [h][pb][j] tf32 bits
__device__ float g_gate[HH * BB];                           // [h][b]

// ---------- helpers ----------
__device__ __forceinline__ void cp16(uint32_t dst, const void* src) {
    asm volatile("cp.async.cg.shared.global [%0], [%1], 16;" :: "r"(dst), "l"(src));
}
__device__ __forceinline__ void cp4(uint32_t dst, const void* src) {
    asm volatile("cp.async.ca.shared.global [%0], [%1], 4;" :: "r"(dst), "l"(src));
}
__device__ __forceinline__ void cp_commit() { asm volatile("cp.async.commit_group;"); }
template<int N>
__device__ __forceinline__ void cp_wait() {
    asm volatile("cp.async.wait_group %0;" :: "n"(N));
}
__device__ __forceinline__ uint32_t f2tf(float f) {
    uint32_t r;
    asm("cvt.rna.tf32.f32 %0, %1;" : "=r"(r) : "f"(f));
    return r;
}
__device__ __forceinline__ void mma8(float* d, uint32_t a0, uint32_t a1,
                                     uint32_t a2, uint32_t a3,
                                     uint32_t b0, uint32_t b1) {
    asm volatile(
        "mma.sync.aligned.m16n8k8.row.col.f32.tf32.tf32.f32 "
        "{%0,%1,%2,%3}, {%4,%5,%6,%7}, {%8,%9}, {%0,%1,%2,%3};"
        : "+f"(d[0]), "+f"(d[1]), "+f"(d[2]), "+f"(d[3])
        : "r"(a0), "r"(a1), "r"(a2), "r"(a3), "r"(b0), "r"(b1));
}

// ---------- prep 1a: layer 1 ----------
__global__ void __launch_bounds__(256, 1)
prep1a_kernel(const float* __restrict__ x,
              const float* __restrict__ feW1, const float* __restrict__ feb1)
{
    int g = blockIdx.x * 8 + (threadIdx.x >> 5);
    int lane = threadIdx.x & 31;
    int b = g >> 7, j = g & 127;
    const float* xr = x + b * 784;
    const float* wr = feW1 + j * 784;
    float s = 0.f;
    #pragma unroll 4
    for (int i = lane; i < 784; i += 32) s = fmaf(xr[i], wr[i], s);
    #pragma unroll
    for (int o = 16; o; o >>= 1) s += __shfl_down_sync(0xFFFFFFFFu, s, o);
    if (lane == 0) g_h1[b * 128 + j] = fmaxf(s + feb1[j], 0.f);
}

// ---------- prep fuse: layer2 + gate + hmid(pb-major, tf32 bits) ----------
__global__ void __launch_bounds__(256, 1)
prep_fuse_kernel(const float* __restrict__ feW2, const float* __restrict__ feb2,
                 const float* __restrict__ gateW, const float* __restrict__ gateb,
                 const float* __restrict__ embeds,
                 const float* __restrict__ genW1, const float* __restrict__ genb1)
{
    int h = blockIdx.x;
    int tid = threadIdx.x;
    __shared__ float s_h1[BB * 128];
    __shared__ float s_w2[FEAT * 128];
    __shared__ float s_feats[BB * FEAT];
    __shared__ float s_emb[PP * EMB];

    for (int i = tid; i < BB * 128; i += 256) s_h1[i] = g_h1[i];
    for (int i = tid; i < FEAT * 128; i += 256) s_w2[i] = feW2[i];
    for (int i = tid; i < PP * EMB; i += 256) s_emb[i] = embeds[i];
    __syncthreads();

    for (int o = tid; o < BB * FEAT; o += 256) {
        int b = o & 7, f = o >> 3;
        float s = feb2[f];
        const float* hr = s_h1 + b * 128;
        const float* wr = s_w2 + f * 128;
        #pragma unroll 8
        for (int j = 0; j < 128; j++) s = fmaf(hr[j], wr[j], s);
        s_feats[b * FEAT + f] = s;
        if (h == 0) g_feats[b * FEAT + f] = s;
    }
    __syncthreads();

    if (h == 0 && tid < 8) {
        int r = tid;
        float lg[8];
        float mx = -1e30f;
        #pragma unroll
        for (int c = 0; c < 8; c++) {
            float s = gateb[c];
            const float* fr = s_feats + r * FEAT;
            const float* wr = gateW + c * FEAT;
            #pragma unroll 8
            for (int k = 0; k < FEAT; k++) s = fmaf(fr[k], wr[k], s);
            lg[c] = s;
            mx = fmaxf(mx, s);
        }
        float den = 0.f;
        #pragma unroll
        for (int c = 0; c < 8; c++) { lg[c] = __expf(lg[c] - mx); den += lg[c]; }
        float inv = 1.f / den;
        #pragma unroll
        for (int c = 0; c < 8; c++) g_gate[r * 8 + c] = lg[c] * inv;
    }

    // hmid for head h, pb-major, stored as tf32 bits
    for (int idx = tid; idx < 32 * GH; idx += 256) {
        int pb = idx >> 5;
        int j = idx & 31;
        int p = pb >> 3, b = pb & 7;
        const float* w = genW1 + (size_t)(h * GH + j) * HIN;
        float s = genb1[h * GH + j];
        const float* fr = s_feats + b * FEAT;
        #pragma unroll 8
        for (int i = 0; i < FEAT; i++) s = fmaf(fr[i], w[i], s);
        const float* er = s_emb + p * EMB;
        #pragma unroll 8
        for (int i = 0; i < EMB; i++) s = fmaf(er[i], w[FEAT + i], s);
        g_hmidPB[h * 1024 + pb * 32 + j] = f2tf(fmaxf(s, 0.f));
    }
}

// ---------- main kernel: tf32 mma.sync, 4-phase/head, single barrier/phase ----------
__global__ void __launch_bounds__(TPB, 3)
main_kernel(const float* __restrict__ genW2, const float* __restrict__ genb2,
            const float* __restrict__ attW,  const float* __restrict__ attb,
            const float* __restrict__ embeds,
            float* __restrict__ out)
{
    extern __shared__ float sm[];
    uint32_t* sm_hin  = reinterpret_cast<uint32_t*>(sm + SM_HIN);   // tf32 bits
    uint32_t* sm_hmid = reinterpret_cast<uint32_t*>(sm + SM_HMID);  // tf32 bits
    float* sm_attb = sm + SM_ATTB;
    float* sm_b2   = sm + SM_B2;
    float* sm_gate = sm + SM_GATE;

    int tid = threadIdx.x;
    int w   = tid >> 5;
    int lane = tid & 31;
    int g   = lane >> 2;      // groupID 0..7
    int tig = lane & 3;       // thread-in-group 0..3
    int t_base = blockIdx.x * NT;

    uint32_t smem_u32 = (uint32_t)__cvta_generic_to_shared(sm);

    // stage phase ph = h*4+c into buffer ph&1
    auto issue_phase = [&](int ph) {
        int h = ph >> 2, c = ph & 3;
        uint32_t chb = smem_u32 + (uint32_t)((ph & 1) * CHBUF) * 4;
        if (c < 3) {
            const float* src = attW + (size_t)h * TT * HIN + c * 32;
            #pragma unroll
            for (int i = 0; i < 8; i++) {
                int v = tid + i * TPB;          // [0, 1024)
                int row = v >> 3, cc = v & 7;
                int tr = t_base + row; if (tr >= TT) tr = TT - 1;
                cp16(chb + (uint32_t)(row * STR + cc * 4) * 4,
                     src + (size_t)tr * HIN + cc * 4);
            }
            if (c == 0) {
                int tr = t_base + tid; if (tr >= TT) tr = TT - 1;
                uint32_t slot = (uint32_t)((h & 1) * 128 + tid) * 4;
                cp4(smem_u32 + (uint32_t)SM_ATTB * 4 + slot, attb  + (size_t)h * TT + tr);
                cp4(smem_u32 + (uint32_t)SM_B2   * 4 + slot, genb2 + (size_t)h * TT + tr);
            }
        } else {
            const float* src = genW2 + (size_t)h * TT * GH;
            #pragma unroll
            for (int i = 0; i < 8; i++) {
                int v = tid + i * TPB;
                int row = v >> 3, cc = v & 7;
                int tr = t_base + row; if (tr >= TT) tr = TT - 1;
                cp16(chb + (uint32_t)(row * STR + cc * 4) * 4,
                     src + (size_t)tr * GH + cc * 4);
            }
            const uint32_t* hs = g_hmidPB + (size_t)h * 1024;
            #pragma unroll
            for (int i = 0; i < 2; i++) {
                int v = tid + i * TPB;          // [0, 256)
                int pb = v >> 3, cc = v & 7;
                cp16(smem_u32 + (uint32_t)(SM_HMID + pb * STR + cc * 4) * 4,
                     hs + pb * 32 + cc * 4);
            }
        }
    };

    issue_phase(0);
    cp_commit();

    // stage hin [pb][k] as tf32 bits (stride 100) + gate
    for (int v = tid; v < 32 * 24; v += TPB) {
        int pb = v / 24, c4 = v % 24;
        int p = pb >> 3, b = pb & 7;
        float4 val = (c4 < 16)
            ? *reinterpret_cast<const float4*>(g_feats + b * FEAT + c4 * 4)
            : *reinterpret_cast<const float4*>(embeds + p * EMB + (c4 - 16) * 4);
        uint32_t* dst = sm_hin + pb * HSTR + c4 * 4;
        dst[0] = f2tf(val.x); dst[1] = f2tf(val.y);
        dst[2] = f2tf(val.z); dst[3] = f2tf(val.w);
    }
    if (tid < HH * BB) sm_gate[tid] = g_gate[tid];

    float zacc[32], wacc[32], acc[32];
    #pragma unroll
    for (int i = 0; i < 32; i++) acc[i] = 0.f;

    for (int ph = 0; ph < 32; ph++) {
        cp_wait<0>();          // copies for phase ph complete (this thread)
        __syncthreads();       // visible to all; compute(ph-1) done
        if (ph < 31) { issue_phase(ph + 1); cp_commit(); }

        int h = ph >> 2, c = ph & 3;
        const float* chb = sm + (ph & 1) * CHBUF;

        if (c < 3) {
            if (c == 0) {
                #pragma unroll
                for (int i = 0; i < 32; i++) zacc[i] = 0.f;
            }
            #pragma unroll
            for (int ks = 0; ks < 4; ks++) {
                int col = ks * 8 + tig;
                uint32_t B0[4], B1[4];
                #pragma unroll
                for (int nt = 0; nt < 4; nt++) {
                    const uint32_t* hp = sm_hin + (nt * 8 + g) * HSTR + c * 32 + col;
                    B0[nt] = hp[0];
                    B1[nt] = hp[4];
                }
                uint32_t A[2][4];
                #pragma unroll
                for (int mt = 0; mt < 2; mt++) {
                    const float* ap  = chb + (w * 32 + mt * 16 + g) * STR + col;
                    const float* ap8 = ap + 8 * STR;
                    A[mt][0] = f2tf(ap[0]);
                    A[mt][1] = f2tf(ap8[0]);
                    A[mt][2] = f2tf(ap[4]);
                    A[mt][3] = f2tf(ap8[4]);
                }
                #pragma unroll
                for (int mt = 0; mt < 2; mt++)
                    #pragma unroll
                    for (int nt = 0; nt < 4; nt++)
                        mma8(&zacc[(mt * 4 + nt) * 4],
                             A[mt][0], A[mt][1], A[mt][2], A[mt][3],
                             B0[nt], B1[nt]);
            }
        } else {
            #pragma unroll
            for (int i = 0; i < 32; i++) wacc[i] = 0.f;
            #pragma unroll
            for (int ks = 0; ks < 4; ks++) {
                int col = ks * 8 + tig;
                uint32_t B0[4], B1[4];
                #pragma unroll
                for (int nt = 0; nt < 4; nt++) {
                    const uint32_t* hp = sm_hmid + (nt * 8 + g) * STR + col;
                    B0[nt] = hp[0];
                    B1[nt] = hp[4];
                }
                uint32_t A[2][4];
                #pragma unroll
                for (int mt = 0; mt < 2; mt++) {
                    const float* ap  = chb + (w * 32 + mt * 16 + g) * STR + col;
                    const float* ap8 = ap + 8 * STR;
                    A[mt][0] = f2tf(ap[0]);
                    A[mt][1] = f2tf(ap8[0]);
                    A[mt][2] = f2tf(ap[4]);
                    A[mt][3] = f2tf(ap8[4]);
                }
                #pragma unroll
                for (int mt = 0; mt < 2; mt++)
                    #pragma unroll
                    for (int nt = 0; nt < 4; nt++)
                        mma8(&wacc[(mt * 4 + nt) * 4],
                             A[mt][0], A[mt][1], A[mt][2], A[mt][3],
                             B0[nt], B1[nt]);
            }

            // ---- epilogue for head h ----
            int par = h & 1;
            float ab[2][2], bb[2][2];
            #pragma unroll
            for (int mt = 0; mt < 2; mt++)
                #pragma unroll
                for (int rr = 0; rr < 2; rr++) {
                    int tl = w * 32 + mt * 16 + rr * 8 + g;
                    ab[mt][rr] = sm_attb[par * 128 + tl];
                    bb[mt][rr] = sm_b2[par * 128 + tl];
                }
            float gr0 = sm_gate[h * BB + 2 * tig];
            float gr1 = sm_gate[h * BB + 2 * tig + 1];
            #pragma unroll
            for (int mt = 0; mt < 2; mt++)
                #pragma unroll
                for (int nt = 0; nt < 4; nt++)
                    #pragma unroll
                    for (int r = 0; r < 4; r++) {
                        int idx = (mt * 4 + nt) * 4 + r;
                        int rr = r >> 1;
                        float z = zacc[idx] + ab[mt][rr];
                        float wv = wacc[idx] + bb[mt][rr];
                        float imp = __fdividef(1.f, 1.f + __expf(-z));
                        float gv = (r & 1) ? gr1 : gr0;
                        acc[idx] = fmaf(wv * imp, gv, acc[idx]);
                    }
        }
    }

    // ---- store: acc fragment layout -> out[b][p][t] ----
    #pragma unroll
    for (int mt = 0; mt < 2; mt++)
        #pragma unroll
        for (int r = 0; r < 4; r++) {
            int tl = w * 32 + mt * 16 + (r >> 1) * 8 + g;
            int t = t_base + tl;
            if (t < TT) {
                int bo = 2 * tig + (r & 1);
                #pragma unroll
                for (int nt = 0; nt < 4; nt++)
                    out[(size_t)bo * (PP * TT) + (size_t)nt * TT + t] =
                        acc[(mt * 4 + nt) * 4 + r];
            }
        }
}

extern "C" void kernel_launch(void* const* d_in, const int* in_sizes, int n_in,
                              void* d_out, int out_size)
{
    const float* x     = (const float*)d_in[0];
    const float* feW1  = (const float*)d_in[1];
    const float* feb1  = (const float*)d_in[2];
    const float* feW2  = (const float*)d_in[3];
    const float* feb2  = (const float*)d_in[4];
    const float* emb   = (const float*)d_in[5];
    const float* genW1 = (const float*)d_in[6];
    const float* genb1 = (const float*)d_in[7];
    const float* genW2 = (const float*)d_in[8];
    const float* genb2 = (const float*)d_in[9];
    const float* attW  = (const float*)d_in[10];
    const float* attb  = (const float*)d_in[11];
    const float* gateW = (const float*)d_in[12];
    const float* gateb = (const float*)d_in[13];
    float* out = (float*)d_out;

    prep1a_kernel<<<128, 256>>>(x, feW1, feb1);
    prep_fuse_kernel<<<8, 256>>>(feW2, feb2, gateW, gateb, emb, genW1, genb1);

    const int SMEM = SM_TOT_F * 4;
    cudaFuncSetAttribute(main_kernel, cudaFuncAttributeMaxDynamicSharedMemorySize, SMEM);
    int grid = (TT + NT - 1) / NT;
    main_kernel<<<grid, TPB, SMEM>>>(genW2, genb2, attW, attb, emb, out);
}